// round 11
// baseline (speedup 1.0000x reference)
#include <cuda_runtime.h>

#define MUL   16
#define DD    4
#define S0    8
#define S1    8
#define SOUT  8
#define NP3   8
#define NP4   4
#define EPB   16          // edges per block-iteration (4 per warp)
#define THREADS 128
#define GRID_BLOCKS 1216  // 152 SMs * 8 resident blocks

#define X1PAD 36
#define WPAD  196

typedef unsigned long long u64;

__device__ int d_meta[6];
__device__ int d_zmask;
__device__ int d_p3pack;
__device__ int d_p4pack;

__global__ void prep_kernel(const int* __restrict__ p3, const int* __restrict__ p4) {
    if (threadIdx.x == 0 && blockIdx.x == 0) {
        unsigned int ent[NP3 + NP4];
        int n = 0, zm = 0;
        for (int so = 0; so < SOUT; ++so) {
            int start = n;
            for (int p = 0; p < NP3; ++p)
                if (p3[p * 3 + 2] == so)
                    ent[n++] = (unsigned)(p3[p * 3 + 0]) | ((unsigned)p << 4) | ((unsigned)so << 8);
            for (int p = 0; p < NP4; ++p)
                if (p4[p * 4 + 3] == so)
                    ent[n++] = (unsigned)(p4[p * 4 + 0]) | ((unsigned)(NP3 + p) << 4) | ((unsigned)so << 8);
            if (n == start) zm |= (1 << so);
            else            ent[n - 1] |= (1u << 12);
        }
        for (int i = 0; i < 6; ++i)
            d_meta[i] = (int)(ent[2 * i] | (ent[2 * i + 1] << 16));
        d_zmask = zm;
        int pp3 = 0, pp4 = 0;
        for (int p = 0; p < NP3; ++p) pp3 |= (p3[p * 3 + 1] & 7) << (3 * p);
        for (int p = 0; p < NP4; ++p) {
            pp4 |= (p4[p * 4 + 1] & 7) << (6 * p);
            pp4 |= (p4[p * 4 + 2] & 7) << (6 * p + 3);
        }
        d_p3pack = pp3;
        d_p4pack = pp4;
    }
}

__device__ __forceinline__ u64 dup2(float x) {
    u64 r;
    asm("mov.b64 %0, {%1, %1};" : "=l"(r) : "r"(__float_as_uint(x)));
    return r;
}
__device__ __forceinline__ u64 fma2(u64 a, u64 b, u64 c) {
    u64 d;
    asm("fma.rn.f32x2 %0, %1, %2, %3;" : "=l"(d) : "l"(a), "l"(b), "l"(c));
    return d;
}
__device__ __forceinline__ float2 unpack2(u64 v) {
    float2 f;
    unsigned lo, hi;
    asm("mov.b64 {%0, %1}, %2;" : "=r"(lo), "=r"(hi) : "l"(v));
    f.x = __uint_as_float(lo); f.y = __uint_as_float(hi);
    return f;
}
__device__ __forceinline__ float fget(const float4& v, int j) {
    switch (j) { case 0: return v.x; case 1: return v.y; case 2: return v.z; default: return v.w; }
}
__device__ __forceinline__ float4 sel8(const float4 a[8], int s) {
    switch (s) {
        case 0: return a[0]; case 1: return a[1];
        case 2: return a[2]; case 3: return a[3];
        case 4: return a[4]; case 5: return a[5];
        case 6: return a[6]; default: return a[7];
    }
}

template <bool FULL>
__global__ __launch_bounds__(THREADS, 8) void tp_kernel(
    const float* __restrict__ x0, const int* __restrict__ i0,
    const float* __restrict__ x1,
    const float* __restrict__ C3, const float* __restrict__ C4,
    float* __restrict__ out, int E)
{
    __shared__ float sC4T[16 * 64];      // [jk][(p,i)*4 + m]
    __shared__ float sC3T[4 * 128];      // [j][job*4 + k]
    __shared__ float sX1[EPB * X1PAD];   // 16 edge rows
    __shared__ float sW[EPB * WPAD];     // 16 edge rows

    const int tid  = threadIdx.x;
    const int warp = tid >> 5;
    const int lane = tid & 31;
    const int u    = tid & 15;
    const int el   = (tid >> 4) & 1;
    const int wq   = warp * 4;           // first local edge of this warp

    for (int idx = tid; idx < 1024; idx += THREADS) {
        int uu = idx >> 6, r = idx & 63, jk = r >> 2, m = r & 3;
        sC4T[jk * 64 + uu * 4 + m] = C4[idx];
    }
    for (int idx = tid; idx < 512; idx += THREADS) {
        int job = idx >> 4, r = idx & 15, j = r >> 2, k = r & 3;
        sC3T[j * 128 + job * 4 + k] = C3[idx];
    }

    int meta[6];
    #pragma unroll
    for (int i = 0; i < 6; ++i) meta[i] = d_meta[i];
    const int zmask = d_zmask;
    const int pp3 = d_p3pack;
    const int pp4 = d_p4pack;

    // fixed job parameters
    const int s1a  = (pp4 >> (6 * (u >> 2))) & 7;       // rank-4 job (p,i)=u, m-half el
    const int s1b  = (pp4 >> (6 * (u >> 2) + 3)) & 7;
    const int job3 = u + 16 * el;                        // rank-3 job
    const int s1c  = (pp3 >> (3 * (job3 >> 2))) & 7;

    __syncthreads();

    const int ngroups = (E + EPB - 1) / EPB;

    for (int g = blockIdx.x; g < ngroups; g += GRID_BLOCKS) {
        const int ebase = g * EPB + wq;

        // ---- stage x1 for this warp's 4 edges (1 LDG.128 + 1 STS.128 per lane) ----
        {
            const int q = lane >> 3;
            int eg = ebase + q;
            if (!FULL) eg = (eg < E) ? eg : (E - 1);
            const float4 v = __ldg((const float4*)&x1[(long long)eg * (S1 * DD) + (lane & 7) * 4]);
            *(float4*)&sX1[(wq + q) * X1PAD + (lane & 7) * 4] = v;
        }
        __syncwarp();

        // ---- W phase: C coefficient outer, 4 edges inner (C read once per 4 edges) ----
        {   // rank-4: thread (u,el) computes W4[(p,i)=u][m = 2el, 2el+1] for 4 edges
            float4 bqa[4], cqa[4];
            #pragma unroll
            for (int q = 0; q < 4; ++q) {
                bqa[q] = *(const float4*)&sX1[(wq + q) * X1PAD + s1a * 4];
                cqa[q] = *(const float4*)&sX1[(wq + q) * X1PAD + s1b * 4];
            }
            u64 w[4] = {0ull, 0ull, 0ull, 0ull};
            #pragma unroll
            for (int jk = 0; jk < 16; ++jk) {
                const int j = jk >> 2, k = jk & 3;
                const u64 cf = *(const u64*)&sC4T[jk * 64 + u * 4 + el * 2];
                #pragma unroll
                for (int q = 0; q < 4; ++q)
                    w[q] = fma2(dup2(fget(bqa[q], j) * fget(cqa[q], k)), cf, w[q]);
            }
            #pragma unroll
            for (int q = 0; q < 4; ++q)
                *(u64*)&sW[(wq + q) * WPAD + 128 + u * 4 + el * 2] = w[q];
        }
        {   // rank-3: thread (u,el) computes full W3 row for job3, 4 edges
            float4 bq3[4];
            #pragma unroll
            for (int q = 0; q < 4; ++q)
                bq3[q] = *(const float4*)&sX1[(wq + q) * X1PAD + s1c * 4];
            u64 w01[4] = {0ull, 0ull, 0ull, 0ull};
            u64 w23[4] = {0ull, 0ull, 0ull, 0ull};
            #pragma unroll
            for (int j = 0; j < 4; ++j) {
                const ulonglong2 cf = *(const ulonglong2*)&sC3T[j * 128 + job3 * 4];
                #pragma unroll
                for (int q = 0; q < 4; ++q) {
                    const u64 bj = dup2(fget(bq3[q], j));
                    w01[q] = fma2(bj, cf.x, w01[q]);
                    w23[q] = fma2(bj, cf.y, w23[q]);
                }
            }
            #pragma unroll
            for (int q = 0; q < 4; ++q)
                *(ulonglong2*)&sW[(wq + q) * WPAD + job3 * 4] = make_ulonglong2(w01[q], w23[q]);
        }
        __syncwarp();

        // ---- contraction: 2 passes, half-warp per edge ----
        #pragma unroll
        for (int pp = 0; pp < 2; ++pp) {
            const int q = 2 * pp + el;
            const int e = ebase + q;
            const bool valid = FULL ? true : (e < E);
            const int ec = FULL ? e : (valid ? e : (E - 1));

            float4 a[8];
            const long long row = (long long)__ldg(&i0[ec]) * (S0 * MUL * DD);
            #pragma unroll
            for (int c = 0; c < 8; ++c)
                a[c] = __ldg((const float4*)&x0[row + c * 64 + u * 4]);

            const float* myW = &sW[(wq + q) * WPAD];
            const long long obase = (long long)e * (SOUT * MUL * DD);
            u64 acc01 = 0ull, acc23 = 0ull;
            #pragma unroll
            for (int t = 0; t < 12; ++t) {
                const int w16  = (meta[t >> 1] >> ((t & 1) * 16)) & 0xffff;
                const int s0v  = w16 & 7;
                const int slot = (w16 >> 4) & 15;
                const float4 av = sel8(a, s0v);
                const ulonglong2 W0 = *(const ulonglong2*)&myW[slot * 16];
                const ulonglong2 W1 = *(const ulonglong2*)&myW[slot * 16 + 4];
                const ulonglong2 W2 = *(const ulonglong2*)&myW[slot * 16 + 8];
                const ulonglong2 W3 = *(const ulonglong2*)&myW[slot * 16 + 12];
                acc01 = fma2(dup2(av.x), W0.x, acc01); acc23 = fma2(dup2(av.x), W0.y, acc23);
                acc01 = fma2(dup2(av.y), W1.x, acc01); acc23 = fma2(dup2(av.y), W1.y, acc23);
                acc01 = fma2(dup2(av.z), W2.x, acc01); acc23 = fma2(dup2(av.z), W2.y, acc23);
                acc01 = fma2(dup2(av.w), W3.x, acc01); acc23 = fma2(dup2(av.w), W3.y, acc23);
                if (w16 & (1 << 12)) {
                    const int so = (w16 >> 8) & 7;
                    if (valid) {
                        const float2 lo = unpack2(acc01);
                        const float2 hi = unpack2(acc23);
                        __stwt((float4*)&out[obase + so * 64 + u * 4],
                               make_float4(lo.x, lo.y, hi.x, hi.y));
                    }
                    acc01 = 0ull; acc23 = 0ull;
                }
            }
            if (valid && zmask) {
                const float4 z = make_float4(0.f, 0.f, 0.f, 0.f);
                #pragma unroll
                for (int so = 0; so < SOUT; ++so)
                    if ((zmask >> so) & 1)
                        __stwt((float4*)&out[obase + so * 64 + u * 4], z);
            }
        }
        __syncwarp();   // protect sX1/sW reuse next iteration
    }
}

extern "C" void kernel_launch(void* const* d_in, const int* in_sizes, int n_in,
                              void* d_out, int out_size) {
    const float* x0 = (const float*)d_in[0];
    const int*   i0 = (const int*)d_in[1];
    const float* x1 = (const float*)d_in[2];
    const float* C3 = (const float*)d_in[3];
    const float* C4 = (const float*)d_in[4];
    const int*   p3 = (const int*)d_in[5];
    const int*   p4 = (const int*)d_in[6];
    float* out = (float*)d_out;
    const int E = in_sizes[1];

    prep_kernel<<<1, 32>>>(p3, p4);
    const int ngroups = (E + EPB - 1) / EPB;
    const int blocks = ngroups < GRID_BLOCKS ? ngroups : GRID_BLOCKS;
    if (E % EPB == 0)
        tp_kernel<true><<<blocks, THREADS>>>(x0, i0, x1, C3, C4, out, E);
    else
        tp_kernel<false><<<blocks, THREADS>>>(x0, i0, x1, C3, C4, out, E);
}